// round 1
// baseline (speedup 1.0000x reference)
#include <cuda_runtime.h>
#include <cuda_bf16.h>
#include <cstdint>

// DynamicMaskHead: 128 instances, per-instance MLP 10 -> 8 -> 8 -> 1 over
// 160x160 pixels. features [1, 128*10, 160, 160] f32, params [128, 169] f32,
// out [128, 1, 160, 160] f32.
//
// Memory-bound problem (144 MB total traffic). Packed fma.rn.f32x2 keeps the
// FMA pipe under the HBM floor.

#define NINST 128
#define CIN   10
#define CMID  8
#define HW    25600          // 160*160
#define HW4   (HW / 4)       // 6400 float4 pixels per instance
#define TPB   256

// Packed fp32x2 FMA (Blackwell FFMA2) — only reachable via PTX.
__device__ __forceinline__ float2 ffma2(float2 a, float2 b, float2 c) {
    float2 d;
    asm("fma.rn.f32x2 %0, %1, %2, %3;"
        : "=l"(reinterpret_cast<unsigned long long&>(d))
        : "l"(reinterpret_cast<unsigned long long&>(a)),
          "l"(reinterpret_cast<unsigned long long&>(b)),
          "l"(reinterpret_cast<unsigned long long&>(c)));
    return d;
}

__device__ __forceinline__ float2 relu2(float2 a) {
    return make_float2(fmaxf(a.x, 0.0f), fmaxf(a.y, 0.0f));
}

__global__ void __launch_bounds__(TPB)
mask_head_kernel(const float* __restrict__ feat,
                 const float* __restrict__ params,
                 float* __restrict__ out) {
    // Weights duplicated into both halves of a float2 so a single LDS.64
    // feeds fma.rn.f32x2 directly (no per-use packing MOVs).
    __shared__ float2 w0s[CMID * CIN];   // 80
    __shared__ float2 w1s[CMID * CMID];  // 64
    __shared__ float2 w2s[CMID];         // 8
    __shared__ float2 b0s[CMID];
    __shared__ float2 b1s[CMID];
    __shared__ float2 b2s;

    const int inst = blockIdx.y;
    const float* p = params + inst * 169;
    for (int i = threadIdx.x; i < 169; i += TPB) {
        float v = p[i];
        float2 vv = make_float2(v, v);
        if      (i < 80)  w0s[i]       = vv;
        else if (i < 144) w1s[i - 80]  = vv;
        else if (i < 152) w2s[i - 144] = vv;
        else if (i < 160) b0s[i - 152] = vv;
        else if (i < 168) b1s[i - 160] = vv;
        else              b2s          = vv;
    }
    __syncthreads();

    const int p4 = blockIdx.x * TPB + threadIdx.x;   // 0 .. HW4-1

    // features[inst, k, pix]: channel stride = HW floats = HW4 float4
    const float4* fbase =
        reinterpret_cast<const float4*>(feat) + (size_t)inst * CIN * HW4 + p4;

    // Load 4 pixels x 10 channels, split into two f32x2 lanes.
    float2 xa[CIN], xb[CIN];
#pragma unroll
    for (int k = 0; k < CIN; k++) {
        float4 v = fbase[(size_t)k * HW4];
        xa[k] = make_float2(v.x, v.y);
        xb[k] = make_float2(v.z, v.w);
    }

    // Layer 0: 10 -> 8, ReLU
    float2 h0a[CMID], h0b[CMID];
#pragma unroll
    for (int o = 0; o < CMID; o++) {
        float2 aa = b0s[o];
        float2 ab = b0s[o];
#pragma unroll
        for (int k = 0; k < CIN; k++) {
            float2 w = w0s[o * CIN + k];
            aa = ffma2(w, xa[k], aa);
            ab = ffma2(w, xb[k], ab);
        }
        h0a[o] = relu2(aa);
        h0b[o] = relu2(ab);
    }

    // Layer 1: 8 -> 8, ReLU
    float2 h1a[CMID], h1b[CMID];
#pragma unroll
    for (int o = 0; o < CMID; o++) {
        float2 aa = b1s[o];
        float2 ab = b1s[o];
#pragma unroll
        for (int k = 0; k < CMID; k++) {
            float2 w = w1s[o * CMID + k];
            aa = ffma2(w, h0a[k], aa);
            ab = ffma2(w, h0b[k], ab);
        }
        h1a[o] = relu2(aa);
        h1b[o] = relu2(ab);
    }

    // Layer 2: 8 -> 1, no ReLU
    float2 oa = b2s;
    float2 ob = b2s;
#pragma unroll
    for (int k = 0; k < CMID; k++) {
        float2 w = w2s[k];
        oa = ffma2(w, h1a[k], oa);
        ob = ffma2(w, h1b[k], ob);
    }

    float4 res = make_float4(oa.x, oa.y, ob.x, ob.y);
    reinterpret_cast<float4*>(out)[(size_t)inst * HW4 + p4] = res;
}

extern "C" void kernel_launch(void* const* d_in, const int* in_sizes, int n_in,
                              void* d_out, int out_size) {
    const float* feat   = (const float*)d_in[0];
    const float* params = (const float*)d_in[1];
    float* out          = (float*)d_out;

    dim3 grid(HW4 / TPB, NINST);   // (25, 128)
    mask_head_kernel<<<grid, TPB>>>(feat, params, out);
}

// round 2
// speedup vs baseline: 1.3285x; 1.3285x over previous
#include <cuda_runtime.h>
#include <cuda_bf16.h>
#include <cstdint>

// DynamicMaskHead: 128 instances, per-instance MLP 10 -> 8 -> 8 -> 1 over
// 160x160 pixels (fp32). 8 pixels per thread; layers 1+2 fused so h1 is
// never materialized. Packed fma.rn.f32x2 throughout.

#define NINST 128
#define CIN   10
#define CMID  8
#define HW    25600          // 160*160
#define HW8   (HW / 8)       // 3200 8-pixel groups per instance
#define TPB   128

__device__ __forceinline__ float2 ffma2(float2 a, float2 b, float2 c) {
    float2 d;
    asm("fma.rn.f32x2 %0, %1, %2, %3;"
        : "=l"(reinterpret_cast<unsigned long long&>(d))
        : "l"(reinterpret_cast<unsigned long long&>(a)),
          "l"(reinterpret_cast<unsigned long long&>(b)),
          "l"(reinterpret_cast<unsigned long long&>(c)));
    return d;
}

__device__ __forceinline__ float2 relu2(float2 a) {
    return make_float2(fmaxf(a.x, 0.0f), fmaxf(a.y, 0.0f));
}

__global__ void __launch_bounds__(TPB)
mask_head_kernel(const float* __restrict__ feat,
                 const float* __restrict__ params,
                 float* __restrict__ out) {
    // Weights duplicated into both float2 halves: one LDS.64 feeds fma.rn.f32x2.
    __shared__ float2 w0s[CMID * CIN];   // 80
    __shared__ float2 w1s[CMID * CMID];  // 64
    __shared__ float2 w2s[CMID];         // 8
    __shared__ float2 b0s[CMID];
    __shared__ float2 b1s[CMID];
    __shared__ float2 b2s;

    const int inst = blockIdx.y;
    const float* p = params + inst * 169;
    for (int i = threadIdx.x; i < 169; i += TPB) {
        float v = p[i];
        float2 vv = make_float2(v, v);
        if      (i < 80)  w0s[i]       = vv;
        else if (i < 144) w1s[i - 80]  = vv;
        else if (i < 152) w2s[i - 144] = vv;
        else if (i < 160) b0s[i - 152] = vv;
        else if (i < 168) b1s[i - 160] = vv;
        else              b2s          = vv;
    }
    __syncthreads();

    const int g8 = blockIdx.x * TPB + threadIdx.x;   // 0 .. HW8-1
    // features[inst, k, pix]; this thread owns pixels [g8*8, g8*8+8)
    const float4* fbase =
        reinterpret_cast<const float4*>(feat)
        + ((size_t)inst * CIN * HW + (size_t)g8 * 8) / 4;

    // ---- Layer 0 (10 -> 8, ReLU), streaming over input channels ----
    float2 h0[CMID][4];
#pragma unroll
    for (int o = 0; o < CMID; o++) {
        float2 b = b0s[o];
#pragma unroll
        for (int j = 0; j < 4; j++) h0[o][j] = b;
    }

#pragma unroll
    for (int k = 0; k < CIN; k++) {
        float4 v0 = fbase[(size_t)k * (HW / 4)];
        float4 v1 = fbase[(size_t)k * (HW / 4) + 1];
        float2 x[4] = { make_float2(v0.x, v0.y), make_float2(v0.z, v0.w),
                        make_float2(v1.x, v1.y), make_float2(v1.z, v1.w) };
#pragma unroll
        for (int o = 0; o < CMID; o++) {
            float2 w = w0s[o * CIN + k];
#pragma unroll
            for (int j = 0; j < 4; j++) h0[o][j] = ffma2(w, x[j], h0[o][j]);
        }
    }
#pragma unroll
    for (int o = 0; o < CMID; o++)
#pragma unroll
        for (int j = 0; j < 4; j++) h0[o][j] = relu2(h0[o][j]);

    // ---- Layers 1+2 fused: h1[o] computed then folded into final acc ----
    float2 acc[4];
    {
        float2 b = b2s;
#pragma unroll
        for (int j = 0; j < 4; j++) acc[j] = b;
    }

#pragma unroll
    for (int o = 0; o < CMID; o++) {
        float2 t[4];
        float2 b = b1s[o];
#pragma unroll
        for (int j = 0; j < 4; j++) t[j] = b;
#pragma unroll
        for (int k = 0; k < CMID; k++) {
            float2 w = w1s[o * CMID + k];
#pragma unroll
            for (int j = 0; j < 4; j++) t[j] = ffma2(w, h0[k][j], t[j]);
        }
        float2 w2 = w2s[o];
#pragma unroll
        for (int j = 0; j < 4; j++) acc[j] = ffma2(w2, relu2(t[j]), acc[j]);
    }

    float4* obase = reinterpret_cast<float4*>(out)
                    + ((size_t)inst * HW + (size_t)g8 * 8) / 4;
    obase[0] = make_float4(acc[0].x, acc[0].y, acc[1].x, acc[1].y);
    obase[1] = make_float4(acc[2].x, acc[2].y, acc[3].x, acc[3].y);
}

extern "C" void kernel_launch(void* const* d_in, const int* in_sizes, int n_in,
                              void* d_out, int out_size) {
    const float* feat   = (const float*)d_in[0];
    const float* params = (const float*)d_in[1];
    float* out          = (float*)d_out;

    dim3 grid(HW8 / TPB, NINST);   // (25, 128)
    mask_head_kernel<<<grid, TPB>>>(feat, params, out);
}